// round 2
// baseline (speedup 1.0000x reference)
#include <cuda_runtime.h>

#define BB 8
#define NN 2048
#define DD 128
#define LL 3
#define ALPHA 0.2f
#define NEG_INF -9e15f
#define NW 64  /* 32-bit words per adjacency row (N/32) */

// Scratch (device globals: no allocation allowed in kernel_launch)
__device__ float    g_h [BB * NN * DD];      // 8 MB: h = relu(xW+b)
__device__ float    g_s1[BB * NN];
__device__ float    g_s2[BB * NN];
__device__ float    g_m [BB * NN];           // per-row masked max of e
__device__ unsigned g_bits[BB * NN * NW];    // 4 MB: packed adjacency

// ---------------------------------------------------------------------------
// K0: pack adj (int32 {0,1}) into bitmask. One thread per element, ballot.
// ---------------------------------------------------------------------------
__global__ __launch_bounds__(256) void pack_adj_kernel(const int* __restrict__ adj)
{
    int idx = blockIdx.x * 256 + threadIdx.x;       // < B*N*N
    unsigned bit = (adj[idx] > 0) ? 1u : 0u;
    unsigned word = __ballot_sync(0xffffffffu, bit);
    if ((threadIdx.x & 31) == 0) g_bits[idx >> 5] = word;
}

// ---------------------------------------------------------------------------
// K1: h = relu(x @ W + b); s1 = h.a1; s2 = h.a2
// Block: 64 rows x 128 cols, 256 threads, 4x8 register tile per thread.
// ---------------------------------------------------------------------------
__global__ __launch_bounds__(256) void gemm_h_kernel(
    const float* __restrict__ x, const float* __restrict__ Wg,
    const float* __restrict__ bg, const float* __restrict__ aa, int layer)
{
    __shared__ float x_s[64][33];    // pitch 33 -> conflict-free
    __shared__ float W_s[32][128];

    const float* W    = Wg + layer * DD * DD;
    const float* bias = bg + layer * DD;
    const float* a1   = aa + layer * 2 * DD;
    const float* a2   = a1 + DD;

    int t   = threadIdx.x;
    int tr  = t >> 4;        // 0..15  (row group: rows tr*4 .. tr*4+3)
    int tc  = t & 15;        // 0..15  (col group: cols tc + 16u)
    int row0 = blockIdx.x * 64;

    float acc[4][8];
#pragma unroll
    for (int i = 0; i < 4; i++)
#pragma unroll
        for (int u = 0; u < 8; u++) acc[i][u] = 0.f;

    for (int kc = 0; kc < 4; kc++) {
        __syncthreads();
        // load x chunk: 64 rows x 32 k  (8 floats/thread, scalar smem stores)
        {
            int r = t >> 2, q = t & 3;
            const float4* src = (const float4*)(x + (size_t)(row0 + r) * DD + kc * 32 + q * 8);
            float4 v0 = src[0], v1 = src[1];
            float* dst = &x_s[r][q * 8];
            dst[0] = v0.x; dst[1] = v0.y; dst[2] = v0.z; dst[3] = v0.w;
            dst[4] = v1.x; dst[5] = v1.y; dst[6] = v1.z; dst[7] = v1.w;
        }
        // load W chunk: 32 k x 128 d  (1024 float4 / 256 threads = 4 each)
#pragma unroll
        for (int p = 0; p < 4; p++) {
            int i = t + 256 * p;
            int k = i >> 5, dq = (i & 31) * 4;
            *(float4*)&W_s[k][dq] = *(const float4*)(W + (size_t)(kc * 32 + k) * DD + dq);
        }
        __syncthreads();
#pragma unroll
        for (int k = 0; k < 32; k++) {
            float xv[4], wv[8];
#pragma unroll
            for (int i = 0; i < 4; i++) xv[i] = x_s[tr * 4 + i][k];
#pragma unroll
            for (int u = 0; u < 8; u++) wv[u] = W_s[k][tc + (u << 4)];
#pragma unroll
            for (int i = 0; i < 4; i++)
#pragma unroll
                for (int u = 0; u < 8; u++)
                    acc[i][u] = fmaf(xv[i], wv[u], acc[i][u]);
        }
    }

    // epilogue: bias + relu, store h, reduce s1/s2 across the 16 tc lanes
    float bv[8], a1v[8], a2v[8];
#pragma unroll
    for (int u = 0; u < 8; u++) {
        int d = tc + (u << 4);
        bv[u] = bias[d]; a1v[u] = a1[d]; a2v[u] = a2[d];
    }
#pragma unroll
    for (int i = 0; i < 4; i++) {
        int row = row0 + tr * 4 + i;
        float p1 = 0.f, p2 = 0.f;
#pragma unroll
        for (int u = 0; u < 8; u++) {
            float hv = acc[i][u] + bv[u];
            hv = fmaxf(hv, 0.f);
            g_h[(size_t)row * DD + tc + (u << 4)] = hv;
            p1 = fmaf(hv, a1v[u], p1);
            p2 = fmaf(hv, a2v[u], p2);
        }
        // tc lanes 0..15 are contiguous within a half-warp -> width-16 shuffle
#pragma unroll
        for (int off = 8; off; off >>= 1) {
            p1 += __shfl_xor_sync(0xffffffffu, p1, off, 16);
            p2 += __shfl_xor_sync(0xffffffffu, p2, off, 16);
        }
        if (tc == 0) { g_s1[row] = p1; g_s2[row] = p2; }
    }
}

// ---------------------------------------------------------------------------
// K2: per-row masked max.  m_i = lrelu(s1_i + max_{adj[i][j]=1} s2_j),
//     or NEG_INF if the row is fully masked.  One warp per row.
// ---------------------------------------------------------------------------
__global__ __launch_bounds__(256) void rowmax_kernel()
{
    int row  = blockIdx.x * 8 + (threadIdx.x >> 5);  // global row in [0, B*N)
    int lane = threadIdx.x & 31;
    int batch = row >> 11;
    const unsigned* bits = g_bits + (size_t)row * NW;
    const float*    s2   = g_s2 + (batch << 11);

    float mx = -3.0e38f;
#pragma unroll 4
    for (int w = 0; w < NW; w++) {
        unsigned word = bits[w];              // broadcast load
        float v = s2[(w << 5) + lane];        // coalesced
        if ((word >> lane) & 1u) mx = fmaxf(mx, v);
    }
#pragma unroll
    for (int off = 16; off; off >>= 1)
        mx = fmaxf(mx, __shfl_xor_sync(0xffffffffu, mx, off));

    if (lane == 0) {
        float m;
        if (mx < -1.0e38f) {
            m = NEG_INF;                       // fully masked row
        } else {
            float e = g_s1[row] + mx;
            m = (e > 0.f) ? e : ALPHA * e;     // lrelu is monotone -> max commutes
        }
        g_m[row] = m;
    }
}

// ---------------------------------------------------------------------------
// K3: fused masked-softmax @ h  + residual.
// Grid (N/64, B). Block 256 threads computes 64 rows x 128 cols.
// Per 32-j chunk: load h tile + bit words, compute w = exp(e - m) into smem,
// then 4x8 register-tile rank-1 updates. Z accumulated alongside.
// ---------------------------------------------------------------------------
__global__ __launch_bounds__(256) void attn_kernel(float* __restrict__ xio)
{
    __shared__ float    h_s[32][128];
    __shared__ float    w_s[32][65];      // pitch 65 -> conflict-free writes
    __shared__ float    s1_s[64], m_s[64], Z_s[64];
    __shared__ unsigned bits_s[64];

    int t  = threadIdx.x;
    int tr = t >> 4, tc = t & 15;
    int batch = blockIdx.y;
    int row0  = blockIdx.x * 64;
    int grow0 = (batch << 11) + row0;

    const float* hB  = g_h  + (size_t)(batch << 11) * DD;
    const float* s2B = g_s2 + (batch << 11);

    if (t < 64) { s1_s[t] = g_s1[grow0 + t]; m_s[t] = g_m[grow0 + t]; }

    float acc[4][8];
#pragma unroll
    for (int i = 0; i < 4; i++)
#pragma unroll
        for (int u = 0; u < 8; u++) acc[i][u] = 0.f;
    float accz[4] = {0.f, 0.f, 0.f, 0.f};

    for (int jc = 0; jc < 64; jc++) {
        __syncthreads();   // prior phase2 done reading h_s/w_s
        // load h tile: 32 x 128 = 1024 float4 / 256 threads
        {
            const float4* src = (const float4*)(hB + (size_t)jc * 32 * DD);
            float4* dst = (float4*)&h_s[0][0];
#pragma unroll
            for (int p = 0; p < 4; p++) dst[t + 256 * p] = src[t + 256 * p];
        }
        if (t < 64) bits_s[t] = g_bits[(size_t)(grow0 + t) * NW + jc];
        __syncthreads();
        // phase 1: w_s[j][r] = exp(e - m)   (masked -> exact 0; all-masked -> 1)
        {
            int j  = t >> 3;
            int rb = (t & 7) << 3;
            float s2v = s2B[(jc << 5) + j];
#pragma unroll
            for (int u = 0; u < 8; u++) {
                int r = rb + u;
                float e = s1_s[r] + s2v;
                e = (e > 0.f) ? e : ALPHA * e;
                float earg = ((bits_s[r] >> j) & 1u) ? e : NEG_INF;
                w_s[j][r] = __expf(earg - m_s[r]);
            }
        }
        __syncthreads();
        // phase 2: rank-1 updates
#pragma unroll 8
        for (int j = 0; j < 32; j++) {
            float w0 = w_s[j][tr * 4 + 0];
            float w1 = w_s[j][tr * 4 + 1];
            float w2 = w_s[j][tr * 4 + 2];
            float w3 = w_s[j][tr * 4 + 3];
            float hv[8];
#pragma unroll
            for (int u = 0; u < 8; u++) hv[u] = h_s[j][tc + (u << 4)];
#pragma unroll
            for (int u = 0; u < 8; u++) {
                acc[0][u] = fmaf(w0, hv[u], acc[0][u]);
                acc[1][u] = fmaf(w1, hv[u], acc[1][u]);
                acc[2][u] = fmaf(w2, hv[u], acc[2][u]);
                acc[3][u] = fmaf(w3, hv[u], acc[3][u]);
            }
            if (tc == 0) { accz[0] += w0; accz[1] += w1; accz[2] += w2; accz[3] += w3; }
        }
    }

    if (tc == 0) {
#pragma unroll
        for (int i = 0; i < 4; i++) Z_s[tr * 4 + i] = accz[i];
    }
    __syncthreads();

#pragma unroll
    for (int i = 0; i < 4; i++) {
        int r = tr * 4 + i;
        float invz = 1.0f / Z_s[r];
        size_t base = (size_t)(grow0 + r) * DD;
#pragma unroll
        for (int u = 0; u < 8; u++) {
            int d = tc + (u << 4);
            xio[base + d] = fmaf(acc[i][u], invz, xio[base + d]);
        }
    }
}

// ---------------------------------------------------------------------------
extern "C" void kernel_launch(void* const* d_in, const int* in_sizes, int n_in,
                              void* d_out, int out_size)
{
    const float* x   = (const float*)d_in[0];   // [B,N,D]
    const int*   adj = (const int*)  d_in[1];   // [B,N,N]
    const float* Wg  = (const float*)d_in[2];   // [L,D,D]
    const float* bg  = (const float*)d_in[3];   // [L,D]
    const float* aa  = (const float*)d_in[4];   // [L,2D]
    float* out = (float*)d_out;                 // [B,N,D] -- doubles as evolving x

    // x lives in d_out throughout (residual updates in place)
    cudaMemcpyAsync(out, x, (size_t)BB * NN * DD * sizeof(float),
                    cudaMemcpyDeviceToDevice);

    pack_adj_kernel<<<(BB * NN * NN) / 256, 256>>>(adj);

    for (int l = 0; l < LL; l++) {
        gemm_h_kernel<<<(BB * NN) / 64, 256>>>(out, Wg, bg, aa, l);
        rowmax_kernel<<<(BB * NN) / 8, 256>>>();
        attn_kernel<<<dim3(NN / 64, BB), 256>>>(out);
    }
}